// round 4
// baseline (speedup 1.0000x reference)
#include <cuda_runtime.h>

#define NB 2048
#define NT 128
#define NS 256
#define NH 64
#define NE 32
#define NV 29

// ---------------- precomputed constants (filled by setup_kernel) ----------------
// thread t computes gate j(t) = (t&3)*64 + (t>>2)   (gate index g=t&3 in {i,f,g,o}, h=t>>2)
__device__ float g_wT[128 * 256];   // [k][t]: k<64 -> W_ih[j(t)][32+k] (context), k>=64 -> W_hh[j(t)][k-64]
__device__ float g_lut[NV * 256];   // [v][t] = b_ih[j]+b_hh[j]+sum_e emb[v][e]*W_ih[j][e], j=j(t)
__device__ float g_fcP[128 * 32];   // [k][v]: xc order [context(0..63), h_new(64..127)]; v>=29 -> 0
__device__ float g_fcb[32];

__device__ __forceinline__ float sigf(float x) {
    return __fdividef(1.0f, 1.0f + __expf(-x));
}
__device__ __forceinline__ float tanhfast(float x) {
    return 1.0f - __fdividef(2.0f, __expf(2.0f * x) + 1.0f);
}

__global__ void setup_kernel(const float* __restrict__ emb, const float* __restrict__ W_ih,
                             const float* __restrict__ W_hh, const float* __restrict__ b_ih,
                             const float* __restrict__ b_hh, const float* __restrict__ fc_W,
                             const float* __restrict__ fc_b) {
    const int t = threadIdx.x;
    const int blk = blockIdx.x;
    const int j = (t & 3) * 64 + (t >> 2);   // permuted gate index for thread t
    if (blk < NV) {
        float s = b_ih[j] + b_hh[j];
#pragma unroll
        for (int e = 0; e < NE; e++) s += emb[blk * NE + e] * W_ih[j * (NE + NH) + e];
        g_lut[blk * 256 + t] = s;
    } else if (blk == NV) {
        for (int k = 0; k < 128; k++)
            g_wT[k * 256 + t] = (k < 64) ? W_ih[j * (NE + NH) + NE + k]
                                         : W_hh[j * NH + (k - 64)];
    } else {
        for (int idx = t; idx < 4096; idx += 256) {
            const int k = idx >> 5, v = idx & 31;
            float val = 0.0f;
            if (v < NV) val = (k < 64) ? fc_W[v * 128 + 64 + k] : fc_W[v * 128 + (k - 64)];
            g_fcP[idx] = val;
        }
        if (t < 32) g_fcb[t] = (t < NV) ? fc_b[t] : 0.0f;
    }
}

// ---------------- smem layout (offsets in floats) ----------------
// enc: chunk-padded: addr(s,h) = (s>>6)*4360 + (s&63)*68 + h   (chunk pad shifts banks by 8)
#define ENC_CHUNK 4360
#define OFF_ENC   0        // 3*4360 + 64*68 = 17432 (alloc 17440)
#define OFF_FCP   17440    // 4096 -> 21536
#define OFF_XCA   21536    // 128  [ctx | h], buffer A
#define OFF_XCB   21664    // 128  buffer B
#define OFF_CST   21792    // 64
#define OFF_EDUP  21856    // 4 bank-skewed softmax copies: [c*264 + s], size 1048 (alloc 1056)
#define OFF_LPART 22912    // 256
#define OFF_WSUM  23168    // 8
#define OFF_FCB   23176    // 32
#define OFF_Y     23208    // 128 ints
#define SMEM_FLOATS 23336
#define SMEM_BYTES (SMEM_FLOATS * 4)   // 93344

__global__ void __launch_bounds__(256, 1)
decoder_kernel(const int* __restrict__ y, const float* __restrict__ h0,
               const float* __restrict__ c0, const float* __restrict__ enc,
               float* __restrict__ out) {
    extern __shared__ float sm[];
    float* sEnc   = sm + OFF_ENC;
    float* sFcP   = sm + OFF_FCP;
    float* sXcA   = sm + OFF_XCA;
    float* sXcB   = sm + OFF_XCB;
    float* sCst   = sm + OFF_CST;
    float* sEdup  = sm + OFF_EDUP;
    float* sLpart = sm + OFF_LPART;
    float* sWsum  = sm + OFF_WSUM;
    float* sFcb   = sm + OFF_FCB;
    int*   sY     = (int*)(sm + OFF_Y);

    const int b = blockIdx.x, tid = threadIdx.x;
    const int lane = tid & 31, warp = tid >> 5;

    // one-time loads
    const float* encb = enc + (size_t)b * (NS * NH);
    for (int idx = tid; idx < NS * NH; idx += 256) {
        const int s = idx >> 6, h = idx & 63;
        sEnc[(s >> 6) * ENC_CHUNK + (s & 63) * 68 + h] = encb[idx];
    }
    for (int idx = tid; idx < 4096; idx += 256) sFcP[idx] = g_fcP[idx];
    if (tid < 64) { sXcA[64 + tid] = h0[b * 64 + tid]; sCst[tid] = c0[b * 64 + tid]; }
    if (tid < 128) sY[tid] = y[b * 128 + tid];
    if (tid < 32) sFcb[tid] = g_fcb[tid];

    // per-thread gate-weight column in registers
    float w[128];
#pragma unroll
    for (int k = 0; k < 128; k++) w[k] = g_wT[k * 256 + tid];
    __syncthreads();

    // scores phase: thread owns encoder row s = tid
    const float4* erow = (const float4*)(sEnc + ((tid >> 6) * ENC_CHUNK) + (tid & 63) * 68);
    // context phase: chunk c2 = lane&3 (64 s each), hh2 = tid>>2 reused for gates/cell too
    const int c2  = tid & 3;
    const int hh2 = tid >> 2;                 // 0..63, 8 per warp
    const float* encCtx = sEnc + c2 * ENC_CHUNK + hh2;
    const float* eDup   = sEdup + c2 * 328;   // c*264 + 64*c = 328*c
    // logits phase
    const int lc  = tid >> 5;                 // 8 chunks of 16 k
    const int lk0 = lc << 4;
    const int lv  = tid & 31;

    float* bufs[2] = { sXcA, sXcB };

    for (int t = 0; t < NT; t++) {
        float* bufP = bufs[t & 1];          // holds h_old; ctx_t written here
        float* bufN = bufs[(t + 1) & 1];    // h_new written here
        const float lg = g_lut[sY[t] * 256 + tid];  // early L2 load

        // ---- phase 1: score + exp + warp sum ----
        const float4* hv4 = (const float4*)(bufP + 64);
        float a0 = 0.f, a1 = 0.f, a2 = 0.f, a3 = 0.f;
#pragma unroll
        for (int i = 0; i < 16; i++) {
            const float4 e4 = erow[i];
            const float4 h4 = hv4[i];
            a0 = fmaf(e4.x, h4.x, a0); a1 = fmaf(e4.y, h4.y, a1);
            a2 = fmaf(e4.z, h4.z, a2); a3 = fmaf(e4.w, h4.w, a3);
        }
        const float sc = fminf((a0 + a1) + (a2 + a3), 80.0f);  // |sc|<~45; clamp = NaN safety
        const float ev = __expf(sc);                           // softmax shift-invariant, no overflow
#pragma unroll
        for (int c = 0; c < 4; c++) sEdup[c * 264 + tid] = ev; // 4 bank-skewed copies
        float ss = ev;
#pragma unroll
        for (int o = 16; o > 0; o >>= 1) ss += __shfl_xor_sync(0xffffffffu, ss, o);
        if (lane == 0) sWsum[warp] = ss;
        __syncthreads();   // bar1

        // ---- phase 2: context partials + shfl-combine ----
        float cp0 = 0.f, cp1 = 0.f, cp2 = 0.f, cp3 = 0.f;
#pragma unroll
        for (int i = 0; i < 16; i++) {
            const float4 e4 = *(const float4*)(eDup + 4 * i);
            const float* p = encCtx + i * 272;   // 4 rows * 68
            cp0 = fmaf(e4.x, p[0],   cp0);
            cp1 = fmaf(e4.y, p[68],  cp1);
            cp2 = fmaf(e4.z, p[136], cp2);
            cp3 = fmaf(e4.w, p[204], cp3);
        }
        float cp = (cp0 + cp1) + (cp2 + cp3);
        cp += __shfl_xor_sync(0xffffffffu, cp, 1);
        cp += __shfl_xor_sync(0xffffffffu, cp, 2);
        if ((lane & 3) == 0) {
            float sumE = sWsum[0];
#pragma unroll
            for (int i = 1; i < 8; i++) sumE += sWsum[i];
            bufP[hh2] = cp * __fdividef(1.0f, sumE);
        }
        __syncthreads();   // bar2

        // ---- phase 3: gates (reg weights) + shfl gather + cell ----
        float g0 = lg, g1 = 0.f, g2 = 0.f, g3 = 0.f;
        const float4* xc4 = (const float4*)bufP;
#pragma unroll
        for (int i = 0; i < 32; i++) {
            const float4 x4 = xc4[i];
            g0 = fmaf(x4.x, w[4 * i],     g0);
            g1 = fmaf(x4.y, w[4 * i + 1], g1);
            g2 = fmaf(x4.z, w[4 * i + 2], g2);
            g3 = fmaf(x4.w, w[4 * i + 3], g3);
        }
        const float g = (g0 + g1) + (g2 + g3);
        const int base = lane & ~3;
        const float gi = __shfl_sync(0xffffffffu, g, base + 0);
        const float gf = __shfl_sync(0xffffffffu, g, base + 1);
        const float gg = __shfl_sync(0xffffffffu, g, base + 2);
        const float go = __shfl_sync(0xffffffffu, g, base + 3);
        if ((lane & 3) == 0) {
            const float cn = sigf(gf) * sCst[hh2] + sigf(gi) * tanhfast(gg);
            const float hn = sigf(go) * tanhfast(cn);
            sCst[hh2] = cn;
            bufN[64 + hh2] = hn;   // double-buffer: no race with bufP readers
        }
        __syncthreads();   // bar3

        // ---- phase 4: logits partials (combined = [ctx_t (bufP), h_new (bufN)]) ----
        const float* src = (lc < 4) ? bufP : bufN;
        float lp0 = 0.f, lp1 = 0.f;
        const float4* x4p = (const float4*)(src + lk0);
#pragma unroll
        for (int i = 0; i < 4; i++) {
            const float4 x4 = x4p[i];
            const float* fp = sFcP + (lk0 + 4 * i) * 32 + lv;
            lp0 = fmaf(x4.x, fp[0],  lp0);
            lp1 = fmaf(x4.y, fp[32], lp1);
            lp0 = fmaf(x4.z, fp[64], lp0);
            lp1 = fmaf(x4.w, fp[96], lp1);
        }
        sLpart[tid] = lp0 + lp1;
        __syncthreads();   // bar4

        if (tid < NV) {
            float r = sFcb[tid];
#pragma unroll
            for (int c = 0; c < 8; c++) r += sLpart[c * 32 + tid];
            out[((size_t)b * NT + t) * NV + tid] = r;
        }
        // next write to sLpart (next ph4) separated from this read by bars 1-3
    }
}

extern "C" void kernel_launch(void* const* d_in, const int* in_sizes, int n_in,
                              void* d_out, int out_size) {
    const int*   y      = (const int*)d_in[0];
    const float* h0     = (const float*)d_in[1];
    const float* c0     = (const float*)d_in[2];
    const float* encout = (const float*)d_in[3];
    const float* emb    = (const float*)d_in[4];
    const float* W_ih   = (const float*)d_in[5];
    const float* W_hh   = (const float*)d_in[6];
    const float* b_ih   = (const float*)d_in[7];
    const float* b_hh   = (const float*)d_in[8];
    const float* fc_W   = (const float*)d_in[9];
    const float* fc_b   = (const float*)d_in[10];
    float* out = (float*)d_out;

    cudaFuncSetAttribute(decoder_kernel, cudaFuncAttributeMaxDynamicSharedMemorySize, SMEM_BYTES);

    setup_kernel<<<NV + 2, 256>>>(emb, W_ih, W_hh, b_ih, b_hh, fc_W, fc_b);
    decoder_kernel<<<NB, 256, SMEM_BYTES>>>(y, h0, c0, encout, out);
}

// round 5
// speedup vs baseline: 1.5119x; 1.5119x over previous
#include <cuda_runtime.h>
#include <cuda_fp16.h>

#define NB 2048
#define NT 128
#define NS 256
#define NH 64
#define NE 32
#define NV 29

// ---------------- precomputed constants (filled by setup_kernel) ----------------
__device__ float g_wT[128 * 256];   // [k][j]: k<64 -> W_ih[j][32+k] (context), k>=64 -> W_hh[j][k-64]
__device__ float g_lut[NV * 256];   // [v][j] = b_ih[j]+b_hh[j]+sum_e emb[v][e]*W_ih[j][e]
__device__ float g_fcP[128 * 32];   // [k][v]: xc order [context(0..63), h_new(64..127)]; v>=29 -> 0
__device__ float g_fcb[32];

__device__ __forceinline__ float sigf(float x) {
    return __fdividef(1.0f, 1.0f + __expf(-x));
}
__device__ __forceinline__ float tanhfast(float x) {
    return 1.0f - __fdividef(2.0f, __expf(2.0f * x) + 1.0f);
}

__global__ void setup_kernel(const float* __restrict__ emb, const float* __restrict__ W_ih,
                             const float* __restrict__ W_hh, const float* __restrict__ b_ih,
                             const float* __restrict__ b_hh, const float* __restrict__ fc_W,
                             const float* __restrict__ fc_b) {
    const int t = threadIdx.x;
    const int blk = blockIdx.x;
    if (blk < NV) {
        float s = b_ih[t] + b_hh[t];
#pragma unroll
        for (int e = 0; e < NE; e++) s += emb[blk * NE + e] * W_ih[t * (NE + NH) + e];
        g_lut[blk * 256 + t] = s;
    } else if (blk == NV) {
        for (int k = 0; k < 128; k++)
            g_wT[k * 256 + t] = (k < 64) ? W_ih[t * (NE + NH) + NE + k]
                                         : W_hh[t * NH + (k - 64)];
    } else {
        for (int idx = t; idx < 4096; idx += 256) {
            const int k = idx >> 5, v = idx & 31;
            float val = 0.0f;
            if (v < NV) val = (k < 64) ? fc_W[v * 128 + 64 + k] : fc_W[v * 128 + (k - 64)];
            g_fcP[idx] = val;
        }
        if (t < 32) g_fcb[t] = (t < NV) ? fc_b[t] : 0.0f;
    }
}

// ---------------- smem layout (offsets in floats) ----------------
#define ENC_CHUNK 4360          // fp32 enc: 4 chunks of 64 rows, row stride 68
#define OFF_ENC    0            // 17440
#define OFF_ENC16  17440        // fp16 enc copy [s][h], 256*64 halves = 8192 floats
#define OFF_FCP    25632        // 4096
#define OFF_XC     29728        // 128  [ctx(0..63) | h(64..127)], 16B aligned
#define OFF_CST    29856        // 64
#define OFF_E      29920        // 256  unnormalized softmax weights (warp-local use)
#define OFF_CPART  30176        // 512  [w][h] context partials
#define OFF_LPART  30688        // 256
#define OFF_WSUM   30944        // 8
#define OFF_FCB    30952        // 32
#define OFF_Y      30984        // 128 ints
#define SMEM_FLOATS 31112
#define SMEM_BYTES (SMEM_FLOATS * 4)   // 124448

__global__ void __launch_bounds__(256, 1)
decoder_kernel(const int* __restrict__ y, const float* __restrict__ h0,
               const float* __restrict__ c0, const float* __restrict__ enc,
               float* __restrict__ out) {
    extern __shared__ float sm[];
    float*   sEnc   = sm + OFF_ENC;
    __half*  sEnc16 = (__half*)(sm + OFF_ENC16);
    float*   sFcP   = sm + OFF_FCP;
    float*   sXc    = sm + OFF_XC;
    float*   sCst   = sm + OFF_CST;
    float*   sE     = sm + OFF_E;
    float*   sCpart = sm + OFF_CPART;
    float*   sLpart = sm + OFF_LPART;
    float*   sWsum  = sm + OFF_WSUM;
    float*   sFcb   = sm + OFF_FCB;
    int*     sY     = (int*)(sm + OFF_Y);

    const int b = blockIdx.x, tid = threadIdx.x;
    const int lane = tid & 31, warp = tid >> 5;

    // one-time loads: fp32 padded copy (scores) + fp16 copy (context)
    const float* encb = enc + (size_t)b * (NS * NH);
    for (int idx = tid; idx < NS * NH; idx += 256) {
        const int s = idx >> 6, h = idx & 63;
        const float v = encb[idx];
        sEnc[(s >> 6) * ENC_CHUNK + (s & 63) * 68 + h] = v;
        sEnc16[idx] = __float2half(v);
    }
    for (int idx = tid; idx < 4096; idx += 256) sFcP[idx] = g_fcP[idx];
    if (tid < 64) { sXc[64 + tid] = h0[b * 64 + tid]; sCst[tid] = c0[b * 64 + tid]; }
    if (tid < 128) sY[tid] = y[b * 128 + tid];
    if (tid < 32) sFcb[tid] = g_fcb[tid];

    // per-thread gate-weight column in registers (thread = gate j = tid)
    float w[128];
#pragma unroll
    for (int k = 0; k < 128; k++) w[k] = g_wT[k * 256 + tid];
    __syncthreads();

    // scores phase: thread owns encoder row s = tid (fp32, padded)
    const float4* erow = (const float4*)(sEnc + ((tid >> 6) * ENC_CHUNK) + (tid & 63) * 68);
    // context phase: warp w <-> s-chunk [32w, 32w+32), lane <-> h-pair (bank = lane: conflict-free)
    const __half2* erow2 = (const __half2*)sEnc16 + (warp << 10) + lane;  // (32w)*32 + lane
    const float4*  evW   = (const float4*)(sE + (warp << 5));             // own warp's weights
    // logits phase
    const int lk0 = (tid >> 5) << 4;
    const int lv  = tid & 31;

    for (int t = 0; t < NT; t++) {
        const float lg = g_lut[sY[t] * 256 + tid];  // early L2 load, used in gates phase

        // ---- phase 1: score + exp + warp sum ----
        const float4* hv4 = (const float4*)(sXc + 64);
        float a0 = 0.f, a1 = 0.f, a2 = 0.f, a3 = 0.f;
#pragma unroll
        for (int i = 0; i < 16; i++) {
            const float4 e4 = erow[i];
            const float4 h4 = hv4[i];
            a0 = fmaf(e4.x, h4.x, a0); a1 = fmaf(e4.y, h4.y, a1);
            a2 = fmaf(e4.z, h4.z, a2); a3 = fmaf(e4.w, h4.w, a3);
        }
        const float sc = fminf((a0 + a1) + (a2 + a3), 80.0f);  // |sc|<~45; clamp = NaN safety
        const float ev = __expf(sc);                           // shift-invariant softmax, no overflow
        sE[tid] = ev;
        float ss = ev;
#pragma unroll
        for (int o = 16; o > 0; o >>= 1) ss += __shfl_xor_sync(0xffffffffu, ss, o);
        if (lane == 0) sWsum[warp] = ss;
        __syncwarp();      // phase 2 consumes only this warp's sE slice

        // ---- phase 2: context partials (fp16 enc, warp-local softmax weights) ----
        float2 c0a = {0.f, 0.f}, c1a = {0.f, 0.f}, c2a = {0.f, 0.f}, c3a = {0.f, 0.f};
#pragma unroll
        for (int i4 = 0; i4 < 8; i4++) {
            const float4 e4 = evW[i4];                       // broadcast
            const float2 p0 = __half22float2(erow2[(i4 * 4 + 0) << 5]);
            const float2 p1 = __half22float2(erow2[(i4 * 4 + 1) << 5]);
            const float2 p2 = __half22float2(erow2[(i4 * 4 + 2) << 5]);
            const float2 p3 = __half22float2(erow2[(i4 * 4 + 3) << 5]);
            c0a.x = fmaf(e4.x, p0.x, c0a.x); c0a.y = fmaf(e4.x, p0.y, c0a.y);
            c1a.x = fmaf(e4.y, p1.x, c1a.x); c1a.y = fmaf(e4.y, p1.y, c1a.y);
            c2a.x = fmaf(e4.z, p2.x, c2a.x); c2a.y = fmaf(e4.z, p2.y, c2a.y);
            c3a.x = fmaf(e4.w, p3.x, c3a.x); c3a.y = fmaf(e4.w, p3.y, c3a.y);
        }
        float2 cp;
        cp.x = (c0a.x + c1a.x) + (c2a.x + c3a.x);
        cp.y = (c0a.y + c1a.y) + (c2a.y + c3a.y);
        ((float2*)sCpart)[(warp << 5) + lane] = cp;          // float idx w*64 + 2*lane
        __syncthreads();   // bar2

        // ---- phase 3: combine partials -> normalized context ----
        if (tid < 64) {
            float s0 = sCpart[tid],        s1 = sCpart[64 + tid];
            float s2 = sCpart[128 + tid],  s3 = sCpart[192 + tid];
            float s4 = sCpart[256 + tid],  s5 = sCpart[320 + tid];
            float s6 = sCpart[384 + tid],  s7 = sCpart[448 + tid];
            const float cx = ((s0 + s1) + (s2 + s3)) + ((s4 + s5) + (s6 + s7));
            float sumE = sWsum[0];
#pragma unroll
            for (int i = 1; i < 8; i++) sumE += sWsum[i];
            sXc[tid] = cx * __fdividef(1.0f, sumE);
        }
        __syncthreads();   // bar3

        // ---- phase 4: gates (reg weights, 4-way split) ----
        float g0 = lg, g1 = 0.f, g2 = 0.f, g3 = 0.f;
        const float4* xc4 = (const float4*)sXc;
#pragma unroll
        for (int i = 0; i < 32; i++) {
            const float4 x4 = xc4[i];
            g0 = fmaf(x4.x, w[4 * i],     g0);
            g1 = fmaf(x4.y, w[4 * i + 1], g1);
            g2 = fmaf(x4.z, w[4 * i + 2], g2);
            g3 = fmaf(x4.w, w[4 * i + 3], g3);
        }
        sLpart[tid] = 0.f;  // dead store slot reuse avoided; keep gates in sCpart region? no:
        // store gates into sE (free this phase: last read was phase 2, separated by bar2)
        sE[tid] = (g0 + g1) + (g2 + g3);
        __syncthreads();   // bar4

        // ---- phase 5: LSTM cell update (i, f, g, o) ----
        if (tid < 64) {
            const float gi = sE[tid],        gf = sE[64 + tid];
            const float gg = sE[128 + tid],  go = sE[192 + tid];
            const float cn = sigf(gf) * sCst[tid] + sigf(gi) * tanhfast(gg);
            const float hn = sigf(go) * tanhfast(cn);
            sCst[tid] = cn;
            sXc[64 + tid] = hn;
        }
        __syncthreads();   // bar5

        // ---- phase 6: logits partials (combined = [ctx, h_new] via permuted fcP) ----
        float lp0 = 0.f, lp1 = 0.f;
        const float4* x4p = (const float4*)(sXc + lk0);
#pragma unroll
        for (int i = 0; i < 4; i++) {
            const float4 x4 = x4p[i];
            const float* fp = sFcP + (lk0 + 4 * i) * 32 + lv;
            lp0 = fmaf(x4.x, fp[0],  lp0);
            lp1 = fmaf(x4.y, fp[32], lp1);
            lp0 = fmaf(x4.z, fp[64], lp0);
            lp1 = fmaf(x4.w, fp[96], lp1);
        }
        sLpart[tid] = lp0 + lp1;
        __syncthreads();   // bar6

        // ---- phase 7: final reduce + store ----
        if (tid < NV) {
            float r = sFcb[tid];
#pragma unroll
            for (int c = 0; c < 8; c++) r += sLpart[c * 32 + tid];
            out[((size_t)b * NT + t) * NV + tid] = r;
        }
        // next write to sLpart is in next step's phase 6, separated by bar2..bar5
    }
}

extern "C" void kernel_launch(void* const* d_in, const int* in_sizes, int n_in,
                              void* d_out, int out_size) {
    const int*   y      = (const int*)d_in[0];
    const float* h0     = (const float*)d_in[1];
    const float* c0     = (const float*)d_in[2];
    const float* encout = (const float*)d_in[3];
    const float* emb    = (const float*)d_in[4];
    const float* W_ih   = (const float*)d_in[5];
    const float* W_hh   = (const float*)d_in[6];
    const float* b_ih   = (const float*)d_in[7];
    const float* b_hh   = (const float*)d_in[8];
    const float* fc_W   = (const float*)d_in[9];
    const float* fc_b   = (const float*)d_in[10];
    float* out = (float*)d_out;

    cudaFuncSetAttribute(decoder_kernel, cudaFuncAttributeMaxDynamicSharedMemorySize, SMEM_BYTES);

    setup_kernel<<<NV + 2, 256>>>(emb, W_ih, W_hh, b_ih, b_hh, fc_W, fc_b);
    decoder_kernel<<<NB, 256, SMEM_BYTES>>>(y, h0, c0, encout, out);
}

// round 6
// speedup vs baseline: 1.7356x; 1.1480x over previous
#include <cuda_runtime.h>
#include <cuda_fp16.h>

#define NB 2048
#define NT 128
#define NS 256
#define NH 64
#define NE 32
#define NV 29

// ---------------- precomputed constants (filled by setup_kernel) ----------------
__device__ float g_wT[128 * 256];   // [k][j]: k<64 -> W_ih[j][32+k] (context), k>=64 -> W_hh[j][k-64]
__device__ float g_lut[NV * 256];   // [v][j] = b_ih[j]+b_hh[j]+sum_e emb[v][e]*W_ih[j][e]
__device__ float g_fcP[128 * 32];   // [k][v]: xc order [context(0..63), h_new(64..127)]; v>=29 -> 0
__device__ float g_fcb[32];

__device__ __forceinline__ float sigf(float x) {
    return __fdividef(1.0f, 1.0f + __expf(-x));
}
__device__ __forceinline__ float tanhfast(float x) {
    return 1.0f - __fdividef(2.0f, __expf(2.0f * x) + 1.0f);
}

__global__ void setup_kernel(const float* __restrict__ emb, const float* __restrict__ W_ih,
                             const float* __restrict__ W_hh, const float* __restrict__ b_ih,
                             const float* __restrict__ b_hh, const float* __restrict__ fc_W,
                             const float* __restrict__ fc_b) {
    const int t = threadIdx.x;
    const int blk = blockIdx.x;
    if (blk < NV) {
        float s = b_ih[t] + b_hh[t];
#pragma unroll
        for (int e = 0; e < NE; e++) s += emb[blk * NE + e] * W_ih[t * (NE + NH) + e];
        g_lut[blk * 256 + t] = s;
    } else if (blk == NV) {
        for (int k = 0; k < 128; k++)
            g_wT[k * 256 + t] = (k < 64) ? W_ih[t * (NE + NH) + NE + k]
                                         : W_hh[t * NH + (k - 64)];
    } else {
        for (int idx = t; idx < 4096; idx += 256) {
            const int k = idx >> 5, v = idx & 31;
            float val = 0.0f;
            if (v < NV) val = (k < 64) ? fc_W[v * 128 + 64 + k] : fc_W[v * 128 + (k - 64)];
            g_fcP[idx] = val;
        }
        if (t < 32) g_fcb[t] = (t < NV) ? fc_b[t] : 0.0f;
    }
}

// ---------------- smem layout (offsets in floats) ----------------
// fp16 encoder: row stride 72 halves (144B = 9*16B) -> conflict-free for both
// half8 row reads (scores) and half2 column-pair reads (context)
#define OFF_ENC16  0        // 256*72 halves = 18432 halves = 9216 floats
#define OFF_FCP    9216     // 4096
#define OFF_XC     13312    // 128  [ctx(0..63) | h(64..127)]
#define OFF_CST    13440    // 64
#define OFF_E      13504    // 256  softmax weights; reused for gates in ph4/ph5
#define OFF_CPART  13760    // 512  [w][h] context partials
#define OFF_LPART  14272    // 256
#define OFF_WSUM   14528    // 8
#define OFF_FCB    14536    // 32
#define OFF_Y      14568    // 128 ints
#define SMEM_FLOATS 14696
#define SMEM_BYTES (SMEM_FLOATS * 4)   // 58784

__global__ void __launch_bounds__(256, 1)
decoder_kernel(const int* __restrict__ y, const float* __restrict__ h0,
               const float* __restrict__ c0, const float* __restrict__ enc,
               float* __restrict__ out) {
    extern __shared__ float sm[];
    __half*  sEnc16 = (__half*)(sm + OFF_ENC16);
    float*   sFcP   = sm + OFF_FCP;
    float*   sXc    = sm + OFF_XC;
    float*   sCst   = sm + OFF_CST;
    float*   sE     = sm + OFF_E;
    float*   sCpart = sm + OFF_CPART;
    float*   sLpart = sm + OFF_LPART;
    float*   sWsum  = sm + OFF_WSUM;
    float*   sFcb   = sm + OFF_FCB;
    int*     sY     = (int*)(sm + OFF_Y);

    const int b = blockIdx.x, tid = threadIdx.x;
    const int lane = tid & 31, warp = tid >> 5;

    // one-time loads
    const float* encb = enc + (size_t)b * (NS * NH);
    for (int idx = tid; idx < NS * NH; idx += 256) {
        const int s = idx >> 6, h = idx & 63;
        sEnc16[s * 72 + h] = __float2half(encb[idx]);
    }
    for (int idx = tid; idx < 4096; idx += 256) sFcP[idx] = g_fcP[idx];
    if (tid < 64) { sXc[64 + tid] = h0[b * 64 + tid]; sCst[tid] = c0[b * 64 + tid]; }
    if (tid < 128) sY[tid] = y[b * 128 + tid];
    if (tid < 32) sFcb[tid] = g_fcb[tid];

    // per-thread gate-weight column in registers (thread = gate j = tid)
    float w[128];
#pragma unroll
    for (int k = 0; k < 128; k++) w[k] = g_wT[k * 256 + tid];
    __syncthreads();

    // scores: thread owns encoder row s = tid (fp16, stride 72 halves, 16B-aligned rows)
    const uint4* erow16 = (const uint4*)(sEnc16 + tid * 72);
    // context: warp w <-> s-chunk [32w,32w+32), lane <-> h-pair (stride 36 half2 per row)
    const __half2* erow2 = (const __half2*)sEnc16 + warp * (32 * 36) + lane;
    const float4*  evW   = (const float4*)(sE + (warp << 5));
    // logits phase
    const int lk0 = (tid >> 5) << 4;
    const int lv  = tid & 31;

    for (int t = 0; t < NT; t++) {
        const float lg = g_lut[sY[t] * 256 + tid];  // L2 load; consumed in phase 4

        // ---- phase 1: fp16 scores + exp + warp sum + gates_h (reuses h loads) ----
        const float4* hv4 = (const float4*)(sXc + 64);
        float a0 = 0.f, a1 = 0.f, a2 = 0.f, a3 = 0.f;
        float gh0 = 0.f, gh1 = 0.f, gh2 = 0.f, gh3 = 0.f;
#pragma unroll
        for (int i = 0; i < 8; i++) {
            const uint4 u = erow16[i];
            const float2 e0 = __half22float2(*(const __half2*)&u.x);
            const float2 e1 = __half22float2(*(const __half2*)&u.y);
            const float2 e2 = __half22float2(*(const __half2*)&u.z);
            const float2 e3 = __half22float2(*(const __half2*)&u.w);
            const float4 ha = hv4[2 * i], hb = hv4[2 * i + 1];
            a0 = fmaf(e0.x, ha.x, a0); a1 = fmaf(e0.y, ha.y, a1);
            a2 = fmaf(e1.x, ha.z, a2); a3 = fmaf(e1.y, ha.w, a3);
            a0 = fmaf(e2.x, hb.x, a0); a1 = fmaf(e2.y, hb.y, a1);
            a2 = fmaf(e3.x, hb.z, a2); a3 = fmaf(e3.y, hb.w, a3);
            gh0 = fmaf(ha.x, w[64 + 8 * i],     gh0);
            gh1 = fmaf(ha.y, w[64 + 8 * i + 1], gh1);
            gh2 = fmaf(ha.z, w[64 + 8 * i + 2], gh2);
            gh3 = fmaf(ha.w, w[64 + 8 * i + 3], gh3);
            gh0 = fmaf(hb.x, w[64 + 8 * i + 4], gh0);
            gh1 = fmaf(hb.y, w[64 + 8 * i + 5], gh1);
            gh2 = fmaf(hb.z, w[64 + 8 * i + 6], gh2);
            gh3 = fmaf(hb.w, w[64 + 8 * i + 7], gh3);
        }
        const float ghSum = (gh0 + gh1) + (gh2 + gh3);
        const float sc = fminf((a0 + a1) + (a2 + a3), 80.0f);  // |sc|<~45; clamp = NaN safety
        const float ev = __expf(sc);                           // shift-invariant softmax
        sE[tid] = ev;
        float ss = ev;
#pragma unroll
        for (int o = 16; o > 0; o >>= 1) ss += __shfl_xor_sync(0xffffffffu, ss, o);
        if (lane == 0) sWsum[warp] = ss;
        __syncwarp();      // phase 2 consumes only this warp's sE slice

        // ---- phase 2: context partials (fp16 enc, warp-local softmax weights) ----
        float2 c0a = {0.f, 0.f}, c1a = {0.f, 0.f}, c2a = {0.f, 0.f}, c3a = {0.f, 0.f};
#pragma unroll
        for (int i4 = 0; i4 < 8; i4++) {
            const float4 e4 = evW[i4];                       // broadcast
            const float2 p0 = __half22float2(erow2[(i4 * 4 + 0) * 36]);
            const float2 p1 = __half22float2(erow2[(i4 * 4 + 1) * 36]);
            const float2 p2 = __half22float2(erow2[(i4 * 4 + 2) * 36]);
            const float2 p3 = __half22float2(erow2[(i4 * 4 + 3) * 36]);
            c0a.x = fmaf(e4.x, p0.x, c0a.x); c0a.y = fmaf(e4.x, p0.y, c0a.y);
            c1a.x = fmaf(e4.y, p1.x, c1a.x); c1a.y = fmaf(e4.y, p1.y, c1a.y);
            c2a.x = fmaf(e4.z, p2.x, c2a.x); c2a.y = fmaf(e4.z, p2.y, c2a.y);
            c3a.x = fmaf(e4.w, p3.x, c3a.x); c3a.y = fmaf(e4.w, p3.y, c3a.y);
        }
        float2 cp;
        cp.x = (c0a.x + c1a.x) + (c2a.x + c3a.x);
        cp.y = (c0a.y + c1a.y) + (c2a.y + c3a.y);
        ((float2*)sCpart)[(warp << 5) + lane] = cp;
        __syncthreads();   // bar2

        // ---- phase 3: combine partials -> normalized context ----
        if (tid < 64) {
            float s0 = sCpart[tid],        s1 = sCpart[64 + tid];
            float s2 = sCpart[128 + tid],  s3 = sCpart[192 + tid];
            float s4 = sCpart[256 + tid],  s5 = sCpart[320 + tid];
            float s6 = sCpart[384 + tid],  s7 = sCpart[448 + tid];
            const float cx = ((s0 + s1) + (s2 + s3)) + ((s4 + s5) + (s6 + s7));
            float sumE = sWsum[0];
#pragma unroll
            for (int i = 1; i < 8; i++) sumE += sWsum[i];
            sXc[tid] = cx * __fdividef(1.0f, sumE);
        }
        __syncthreads();   // bar3

        // ---- phase 4: gates ctx-part only (h-part precomputed in phase 1) ----
        float g0 = lg + ghSum, g1 = 0.f, g2 = 0.f, g3 = 0.f;
        const float4* xc4 = (const float4*)sXc;
#pragma unroll
        for (int i = 0; i < 16; i++) {
            const float4 x4 = xc4[i];
            g0 = fmaf(x4.x, w[4 * i],     g0);
            g1 = fmaf(x4.y, w[4 * i + 1], g1);
            g2 = fmaf(x4.z, w[4 * i + 2], g2);
            g3 = fmaf(x4.w, w[4 * i + 3], g3);
        }
        sE[tid] = (g0 + g1) + (g2 + g3);   // sE free: softmax reads done before bar2
        __syncthreads();   // bar4

        // ---- phase 5: LSTM cell update (i, f, g, o) ----
        if (tid < 64) {
            const float gi = sE[tid],        gf = sE[64 + tid];
            const float gg = sE[128 + tid],  go = sE[192 + tid];
            const float cn = sigf(gf) * sCst[tid] + sigf(gi) * tanhfast(gg);
            const float hn = sigf(go) * tanhfast(cn);
            sCst[tid] = cn;
            sXc[64 + tid] = hn;
        }
        __syncthreads();   // bar5

        // ---- phase 6: logits partials (combined = [ctx, h_new] via permuted fcP) ----
        float lp0 = 0.f, lp1 = 0.f;
        const float4* x4p = (const float4*)(sXc + lk0);
#pragma unroll
        for (int i = 0; i < 4; i++) {
            const float4 x4 = x4p[i];
            const float* fp = sFcP + (lk0 + 4 * i) * 32 + lv;
            lp0 = fmaf(x4.x, fp[0],  lp0);
            lp1 = fmaf(x4.y, fp[32], lp1);
            lp0 = fmaf(x4.z, fp[64], lp0);
            lp1 = fmaf(x4.w, fp[96], lp1);
        }
        sLpart[tid] = lp0 + lp1;
        __syncthreads();   // bar6

        // ---- phase 7: final reduce + store ----
        if (tid < NV) {
            float r = sFcb[tid];
#pragma unroll
            for (int c = 0; c < 8; c++) r += sLpart[c * 32 + tid];
            out[((size_t)b * NT + t) * NV + tid] = r;
        }
        // next write to sLpart is next step's phase 6, separated by bar2..bar5;
        // next write to sE (phase 1) is separated from this step's phase-5 reads by bar5/bar6
    }
}

extern "C" void kernel_launch(void* const* d_in, const int* in_sizes, int n_in,
                              void* d_out, int out_size) {
    const int*   y      = (const int*)d_in[0];
    const float* h0     = (const float*)d_in[1];
    const float* c0     = (const float*)d_in[2];
    const float* encout = (const float*)d_in[3];
    const float* emb    = (const float*)d_in[4];
    const float* W_ih   = (const float*)d_in[5];
    const float* W_hh   = (const float*)d_in[6];
    const float* b_ih   = (const float*)d_in[7];
    const float* b_hh   = (const float*)d_in[8];
    const float* fc_W   = (const float*)d_in[9];
    const float* fc_b   = (const float*)d_in[10];
    float* out = (float*)d_out;

    cudaFuncSetAttribute(decoder_kernel, cudaFuncAttributeMaxDynamicSharedMemorySize, SMEM_BYTES);

    setup_kernel<<<NV + 2, 256>>>(emb, W_ih, W_hh, b_ih, b_hh, fc_W, fc_b);
    decoder_kernel<<<NB, 256, SMEM_BYTES>>>(y, h0, c0, encout, out);
}

// round 12
// speedup vs baseline: 1.9304x; 1.1123x over previous
#include <cuda_runtime.h>
#include <cuda_fp16.h>

#define NB 2048
#define NT 128
#define NS 256
#define NH 64
#define NE 32
#define NV 29

// ---------------- precomputed constants (filled by setup_kernel) ----------------
__device__ float g_wT[128 * 256];   // [k][j]: k<64 -> W_ih[j][32+k] (context), k>=64 -> W_hh[j][k-64]
__device__ float g_lut[NV * 256];   // [v][j] = b_ih[j]+b_hh[j]+sum_e emb[v][e]*W_ih[j][e]
__device__ float g_fcP[128 * 32];   // [k][v]: xc order [context(0..63), h_new(64..127)]; v>=29 -> 0
__device__ float g_fcb[32];

__device__ __forceinline__ float sigf(float x) {
    return __fdividef(1.0f, 1.0f + __expf(-x));
}
__device__ __forceinline__ float tanhfast(float x) {
    return 1.0f - __fdividef(2.0f, __expf(2.0f * x) + 1.0f);
}

__global__ void setup_kernel(const float* __restrict__ emb, const float* __restrict__ W_ih,
                             const float* __restrict__ W_hh, const float* __restrict__ b_ih,
                             const float* __restrict__ b_hh, const float* __restrict__ fc_W,
                             const float* __restrict__ fc_b) {
    const int t = threadIdx.x;
    const int blk = blockIdx.x;
    if (blk < NV) {
        float s = b_ih[t] + b_hh[t];
#pragma unroll
        for (int e = 0; e < NE; e++) s += emb[blk * NE + e] * W_ih[t * (NE + NH) + e];
        g_lut[blk * 256 + t] = s;
    } else if (blk == NV) {
        for (int k = 0; k < 128; k++)
            g_wT[k * 256 + t] = (k < 64) ? W_ih[t * (NE + NH) + NE + k]
                                         : W_hh[t * NH + (k - 64)];
    } else {
        for (int idx = t; idx < 4096; idx += 256) {
            const int k = idx >> 5, v = idx & 31;
            float val = 0.0f;
            if (v < NV) val = (k < 64) ? fc_W[v * 128 + 64 + k] : fc_W[v * 128 + (k - 64)];
            g_fcP[idx] = val;
        }
        if (t < 32) g_fcb[t] = (t < NV) ? fc_b[t] : 0.0f;
    }
}

// ---------------- smem layout (offsets in floats), 2 rows per CTA ----------------
// fp16 encoder per row: row stride 72 halves (144B = 9*16B), conflict-free for
// half8 row reads (scores) and half2 column-pair reads (context).
#define ENC_ROW_HALVES 18432      // 256*72
#define OFF_ENC16  0              // 2 * 9216 floats = 18432
#define OFF_FCP    18432          // 4096
#define OFF_XC     22528          // 2 * 128  [ctx | h]
#define OFF_CST    22784          // 2 * 64
#define OFF_E      22912          // 2 * 256  softmax weights; reused for gates
#define OFF_CPART  23424          // 2 * 512
#define OFF_LPART  24448          // 2 * 256
#define OFF_WSUM   24960          // 2 * 8
#define OFF_FCB    24976          // 32
#define OFF_Y      25008          // 2 * 128 ints
#define SMEM_FLOATS 25264
#define SMEM_BYTES (SMEM_FLOATS * 4)   // 101056

__global__ void __launch_bounds__(256, 1)
decoder_kernel(const int* __restrict__ y, const float* __restrict__ h0,
               const float* __restrict__ c0, const float* __restrict__ enc,
               float* __restrict__ out) {
    extern __shared__ float sm[];
    __half*  sEnc16 = (__half*)(sm + OFF_ENC16);
    float*   sFcP   = sm + OFF_FCP;
    float*   sXc    = sm + OFF_XC;
    float*   sCst   = sm + OFF_CST;
    float*   sE     = sm + OFF_E;
    float*   sCpart = sm + OFF_CPART;
    float*   sLpart = sm + OFF_LPART;
    float*   sWsum  = sm + OFF_WSUM;
    float*   sFcb   = sm + OFF_FCB;
    int*     sY     = (int*)(sm + OFF_Y);

    const int bA = blockIdx.x * 2;          // rows bA, bA+1
    const int tid = threadIdx.x;
    const int lane = tid & 31, warp = tid >> 5;

    // one-time loads (both rows)
    for (int r = 0; r < 2; r++) {
        const float* encb = enc + (size_t)(bA + r) * (NS * NH);
        for (int idx = tid; idx < NS * NH; idx += 256) {
            const int s = idx >> 6, h = idx & 63;
            sEnc16[r * ENC_ROW_HALVES + s * 72 + h] = __float2half(encb[idx]);
        }
        if (tid < 64) {
            sXc[r * 128 + 64 + tid] = h0[(bA + r) * 64 + tid];
            sCst[r * 64 + tid]      = c0[(bA + r) * 64 + tid];
        }
        if (tid < 128) sY[r * 128 + tid] = y[(bA + r) * 128 + tid];
    }
    for (int idx = tid; idx < 4096; idx += 256) sFcP[idx] = g_fcP[idx];
    if (tid < 32) sFcb[tid] = g_fcb[tid];

    // per-thread gate-weight column in registers (shared by both rows)
    float w[128];
#pragma unroll
    for (int k = 0; k < 128; k++) w[k] = g_wT[k * 256 + tid];
    __syncthreads();

    // scores: thread owns encoder row s = tid; row B at +ENC_ROW_HALVES/8 = 2304 uint4
    const uint4*   erow16 = (const uint4*)(sEnc16 + tid * 72);
    // context: warp w <-> s-chunk [32w,32w+32), lane <-> h-pair; row B at +9216 half2
    const __half2* erow2  = (const __half2*)sEnc16 + warp * (32 * 36) + lane;
    const float4*  evW    = (const float4*)(sE + (warp << 5));          // +r*64 float4
    const int lk0 = (tid >> 5) << 4;
    const int lv  = tid & 31;

    for (int t = 0; t < NT; t++) {
        const float lgA = g_lut[sY[t] * 256 + tid];
        const float lgB = g_lut[sY[128 + t] * 256 + tid];

        // ---- phase 1: fp16 scores + exp + warp sum + gates_h, rows A,B ----
        float ghSumA, ghSumB;
#pragma unroll
        for (int r = 0; r < 2; r++) {
            const float4* hv4 = (const float4*)(sXc + r * 128 + 64);
            const uint4*  er  = erow16 + r * 2304;   // row B encoder block
            float a0 = 0.f, a1 = 0.f, a2 = 0.f, a3 = 0.f;
            float gh0 = 0.f, gh1 = 0.f, gh2 = 0.f, gh3 = 0.f;
#pragma unroll
            for (int i = 0; i < 8; i++) {
                const uint4 u = er[i];
                const float2 e0 = __half22float2(*(const __half2*)&u.x);
                const float2 e1 = __half22float2(*(const __half2*)&u.y);
                const float2 e2 = __half22float2(*(const __half2*)&u.z);
                const float2 e3 = __half22float2(*(const __half2*)&u.w);
                const float4 ha = hv4[2 * i], hb = hv4[2 * i + 1];
                a0 = fmaf(e0.x, ha.x, a0); a1 = fmaf(e0.y, ha.y, a1);
                a2 = fmaf(e1.x, ha.z, a2); a3 = fmaf(e1.y, ha.w, a3);
                a0 = fmaf(e2.x, hb.x, a0); a1 = fmaf(e2.y, hb.y, a1);
                a2 = fmaf(e3.x, hb.z, a2); a3 = fmaf(e3.y, hb.w, a3);
                gh0 = fmaf(ha.x, w[64 + 8 * i],     gh0);
                gh1 = fmaf(ha.y, w[64 + 8 * i + 1], gh1);
                gh2 = fmaf(ha.z, w[64 + 8 * i + 2], gh2);
                gh3 = fmaf(ha.w, w[64 + 8 * i + 3], gh3);
                gh0 = fmaf(hb.x, w[64 + 8 * i + 4], gh0);
                gh1 = fmaf(hb.y, w[64 + 8 * i + 5], gh1);
                gh2 = fmaf(hb.z, w[64 + 8 * i + 6], gh2);
                gh3 = fmaf(hb.w, w[64 + 8 * i + 7], gh3);
            }
            if (r == 0) ghSumA = (gh0 + gh1) + (gh2 + gh3);
            else        ghSumB = (gh0 + gh1) + (gh2 + gh3);
            const float sc = fminf((a0 + a1) + (a2 + a3), 80.0f);  // |sc|<~45; NaN safety
            const float ev = __expf(sc);                           // shift-invariant softmax
            sE[r * 256 + tid] = ev;
            float ss = ev;
#pragma unroll
            for (int o = 16; o > 0; o >>= 1) ss += __shfl_xor_sync(0xffffffffu, ss, o);
            if (lane == 0) sWsum[r * 8 + warp] = ss;
        }
        __syncwarp();      // phase 2 consumes only this warp's sE slices

        // ---- phase 2: context partials, rows A,B ----
#pragma unroll
        for (int r = 0; r < 2; r++) {
            const __half2* e2p = erow2 + r * 9216;
            const float4*  ew  = evW + r * 64;
            float2 c0a = {0.f, 0.f}, c1a = {0.f, 0.f}, c2a = {0.f, 0.f}, c3a = {0.f, 0.f};
#pragma unroll
            for (int i4 = 0; i4 < 8; i4++) {
                const float4 e4 = ew[i4];                       // broadcast
                const float2 p0 = __half22float2(e2p[(i4 * 4 + 0) * 36]);
                const float2 p1 = __half22float2(e2p[(i4 * 4 + 1) * 36]);
                const float2 p2 = __half22float2(e2p[(i4 * 4 + 2) * 36]);
                const float2 p3 = __half22float2(e2p[(i4 * 4 + 3) * 36]);
                c0a.x = fmaf(e4.x, p0.x, c0a.x); c0a.y = fmaf(e4.x, p0.y, c0a.y);
                c1a.x = fmaf(e4.y, p1.x, c1a.x); c1a.y = fmaf(e4.y, p1.y, c1a.y);
                c2a.x = fmaf(e4.z, p2.x, c2a.x); c2a.y = fmaf(e4.z, p2.y, c2a.y);
                c3a.x = fmaf(e4.w, p3.x, c3a.x); c3a.y = fmaf(e4.w, p3.y, c3a.y);
            }
            float2 cp;
            cp.x = (c0a.x + c1a.x) + (c2a.x + c3a.x);
            cp.y = (c0a.y + c1a.y) + (c2a.y + c3a.y);
            ((float2*)sCpart)[r * 256 + (warp << 5) + lane] = cp;
        }
        __syncthreads();   // bar2

        // ---- phase 3: combine partials -> normalized context (A: tid<64, B: 64..127) ----
        if (tid < 128) {
            const int r = tid >> 6, hh = tid & 63;
            const float* cpB = sCpart + r * 512;
            float s0 = cpB[hh],        s1 = cpB[64 + hh];
            float s2 = cpB[128 + hh],  s3 = cpB[192 + hh];
            float s4 = cpB[256 + hh],  s5 = cpB[320 + hh];
            float s6 = cpB[384 + hh],  s7 = cpB[448 + hh];
            const float cx = ((s0 + s1) + (s2 + s3)) + ((s4 + s5) + (s6 + s7));
            float sumE = sWsum[r * 8];
#pragma unroll
            for (int i = 1; i < 8; i++) sumE += sWsum[r * 8 + i];
            sXc[r * 128 + hh] = cx * __fdividef(1.0f, sumE);
        }
        __syncthreads();   // bar3

        // ---- phase 4: gates ctx-part (h-part precomputed), rows A,B ----
#pragma unroll
        for (int r = 0; r < 2; r++) {
            float g0 = (r == 0 ? lgA + ghSumA : lgB + ghSumB), g1 = 0.f, g2 = 0.f, g3 = 0.f;
            const float4* xc4 = (const float4*)(sXc + r * 128);
#pragma unroll
            for (int i = 0; i < 16; i++) {
                const float4 x4 = xc4[i];
                g0 = fmaf(x4.x, w[4 * i],     g0);
                g1 = fmaf(x4.y, w[4 * i + 1], g1);
                g2 = fmaf(x4.z, w[4 * i + 2], g2);
                g3 = fmaf(x4.w, w[4 * i + 3], g3);
            }
            sE[r * 256 + tid] = (g0 + g1) + (g2 + g3);  // sE free post-bar2
        }
        __syncthreads();   // bar4

        // ---- phase 5: LSTM cell update (A: tid<64, B: 64..127) ----
        if (tid < 128) {
            const int r = tid >> 6, hh = tid & 63;
            const float* gE = sE + r * 256;
            const float gi = gE[hh],        gf = gE[64 + hh];
            const float gg = gE[128 + hh],  go = gE[192 + hh];
            const float cn = sigf(gf) * sCst[r * 64 + hh] + sigf(gi) * tanhfast(gg);
            const float hn = sigf(go) * tanhfast(cn);
            sCst[r * 64 + hh] = cn;
            sXc[r * 128 + 64 + hh] = hn;
        }
        __syncthreads();   // bar5

        // ---- phase 6: logits partials, rows A,B ----
#pragma unroll
        for (int r = 0; r < 2; r++) {
            float lp0 = 0.f, lp1 = 0.f;
            const float4* x4p = (const float4*)(sXc + r * 128 + lk0);
#pragma unroll
            for (int i = 0; i < 4; i++) {
                const float4 x4 = x4p[i];
                const float* fp = sFcP + (lk0 + 4 * i) * 32 + lv;
                lp0 = fmaf(x4.x, fp[0],  lp0);
                lp1 = fmaf(x4.y, fp[32], lp1);
                lp0 = fmaf(x4.z, fp[64], lp0);
                lp1 = fmaf(x4.w, fp[96], lp1);
            }
            sLpart[r * 256 + tid] = lp0 + lp1;
        }
        __syncthreads();   // bar6

        // ---- phase 7: final reduce + store (row A: warp 0, row B: warp 1) ----
        if (warp < 2 && lane < NV) {
            const int r = warp;
            const float* lpB = sLpart + r * 256;
            float acc = sFcb[lane];
#pragma unroll
            for (int c = 0; c < 8; c++) acc += lpB[c * 32 + lane];
            out[((size_t)(bA + r) * NT + t) * NV + lane] = acc;
        }
        // next write to sLpart is next step ph6 (bar2..bar5 in between);
        // next write to sE (ph1) separated from ph5 reads by bar5/bar6
    }
}

extern "C" void kernel_launch(void* const* d_in, const int* in_sizes, int n_in,
                              void* d_out, int out_size) {
    const int*   y      = (const int*)d_in[0];
    const float* h0     = (const float*)d_in[1];
    const float* c0     = (const float*)d_in[2];
    const float* encout = (const float*)d_in[3];
    const float* emb    = (const float*)d_in[4];
    const float* W_ih   = (const float*)d_in[5];
    const float* W_hh   = (const float*)d_in[6];
    const float* b_ih   = (const float*)d_in[7];
    const float* b_hh   = (const float*)d_in[8];
    const float* fc_W   = (const float*)d_in[9];
    const float* fc_b   = (const float*)d_in[10];
    float* out = (float*)d_out;

    cudaFuncSetAttribute(decoder_kernel, cudaFuncAttributeMaxDynamicSharedMemorySize, SMEM_BYTES);

    setup_kernel<<<NV + 2, 256>>>(emb, W_ih, W_hh, b_ih, b_hh, fc_W, fc_b);
    decoder_kernel<<<NB / 2, 256, SMEM_BYTES>>>(y, h0, c0, encout, out);
}

// round 13
// speedup vs baseline: 2.1206x; 1.0985x over previous
#include <cuda_runtime.h>
#include <cuda_fp16.h>

#define NB 2048
#define NT 128
#define NS 256
#define NH 64
#define NE 32
#define NV 29

// ---------------- precomputed constants (filled by setup_kernel) ----------------
// thread t (0..127) owns gate columns j0=t, j1=t+128.
__device__ __half2 g_wTh[128 * 128];  // [k][t] = half2(W[k][t], W[k][t+128]); k<64: W_ih ctx, k>=64: W_hh
__device__ float2  g_lut2[NV * 128];  // [v][t] = (lut[v][t], lut[v][t+128])
__device__ float   g_fcP[128 * 32];   // [k][v]: xc order [context(0..63), h_new(64..127)]; v>=29 -> 0
__device__ float   g_fcb[32];

__device__ __forceinline__ float sigf(float x) {
    return __fdividef(1.0f, 1.0f + __expf(-x));
}
__device__ __forceinline__ float tanhfast(float x) {
    return 1.0f - __fdividef(2.0f, __expf(2.0f * x) + 1.0f);
}

__global__ void setup_kernel(const float* __restrict__ emb, const float* __restrict__ W_ih,
                             const float* __restrict__ W_hh, const float* __restrict__ b_ih,
                             const float* __restrict__ b_hh, const float* __restrict__ fc_W,
                             const float* __restrict__ fc_b) {
    const int t = threadIdx.x;     // 0..127
    const int blk = blockIdx.x;
    if (blk < NV) {
        float s[2];
#pragma unroll
        for (int c = 0; c < 2; c++) {
            const int j = t + c * 128;
            float acc = b_ih[j] + b_hh[j];
#pragma unroll
            for (int e = 0; e < NE; e++) acc += emb[blk * NE + e] * W_ih[j * (NE + NH) + e];
            s[c] = acc;
        }
        g_lut2[blk * 128 + t] = make_float2(s[0], s[1]);
    } else if (blk == NV) {
        for (int k = 0; k < 128; k++) {
            float w0, w1;
            if (k < 64) {
                w0 = W_ih[t * (NE + NH) + NE + k];
                w1 = W_ih[(t + 128) * (NE + NH) + NE + k];
            } else {
                w0 = W_hh[t * NH + (k - 64)];
                w1 = W_hh[(t + 128) * NH + (k - 64)];
            }
            g_wTh[k * 128 + t] = __floats2half2_rn(w0, w1);
        }
    } else {
        for (int idx = t; idx < 4096; idx += 128) {
            const int k = idx >> 5, v = idx & 31;
            float val = 0.0f;
            if (v < NV) val = (k < 64) ? fc_W[v * 128 + 64 + k] : fc_W[v * 128 + (k - 64)];
            g_fcP[idx] = val;
        }
        if (t < 32) g_fcb[t] = (t < NV) ? fc_b[t] : 0.0f;
    }
}

// ---------------- smem layout (offsets in floats), 1 row per CTA, 128 threads ----------------
// fp16 encoder: row stride 72 halves (144B = 9*16B), conflict-free for both
// half8 row reads (scores) and half2 column-pair reads (context).
#define OFF_ENC16  0        // 256*72 halves = 9216 floats
#define OFF_FCP    9216     // 4096
#define OFF_XC     13312    // 128  [ctx(0..63) | h(64..127)]
#define OFF_CST    13440    // 64
#define OFF_E      13504    // 256  softmax weights; reused for gates
#define OFF_CPART  13760    // 256  (4 warps x 64 h)
#define OFF_LPART  14016    // 128  (4 warps x 32 v)
#define OFF_WSUM   14144    // 8 (4 used)
#define OFF_FCB    14152    // 32
#define OFF_Y      14184    // 128 ints
#define SMEM_FLOATS 14312
#define SMEM_BYTES (SMEM_FLOATS * 4)   // 57248 -> 2 CTAs/SM = 114.5 KB

__global__ void __launch_bounds__(128, 2)
decoder_kernel(const int* __restrict__ y, const float* __restrict__ h0,
               const float* __restrict__ c0, const float* __restrict__ enc,
               float* __restrict__ out) {
    extern __shared__ float sm[];
    __half*  sEnc16 = (__half*)(sm + OFF_ENC16);
    float*   sFcP   = sm + OFF_FCP;
    float*   sXc    = sm + OFF_XC;
    float*   sCst   = sm + OFF_CST;
    float*   sE     = sm + OFF_E;
    float*   sCpart = sm + OFF_CPART;
    float*   sLpart = sm + OFF_LPART;
    float*   sWsum  = sm + OFF_WSUM;
    float*   sFcb   = sm + OFF_FCB;
    int*     sY     = (int*)(sm + OFF_Y);

    const int b = blockIdx.x, tid = threadIdx.x;   // 128 threads
    const int lane = tid & 31, warp = tid >> 5;    // 4 warps

    // one-time loads
    const float* encb = enc + (size_t)b * (NS * NH);
    for (int idx = tid; idx < NS * NH; idx += 128) {
        const int s = idx >> 6, h = idx & 63;
        sEnc16[s * 72 + h] = __float2half(encb[idx]);
    }
    for (int idx = tid; idx < 4096; idx += 128) sFcP[idx] = g_fcP[idx];
    if (tid < 64) { sXc[64 + tid] = h0[b * 64 + tid]; sCst[tid] = c0[b * 64 + tid]; }
    sY[tid] = y[b * 128 + tid];
    if (tid < 32) sFcb[tid] = g_fcb[tid];

    // per-thread packed gate weights: w2[k] = (W[k][tid], W[k][tid+128])
    __half2 w2[128];
#pragma unroll
    for (int k = 0; k < 128; k++) w2[k] = g_wTh[k * 128 + tid];
    __syncthreads();

    // scores: thread owns encoder rows s = tid and s = tid+128
    const uint4* er0 = (const uint4*)(sEnc16 + tid * 72);
    const uint4* er1 = er0 + 1152;                 // +128 rows * 72 halves
    // context: warp w <-> s blocks [32w,32w+32) and [128+32w,...), lane <-> h-pair
    const __half2* e2p  = (const __half2*)sEnc16 + warp * (32 * 36) + lane;
    const __half2* e2pB = e2p + 128 * 36;
    const float4*  ev4  = (const float4*)(sE + (warp << 5));
    const float4*  ev4B = (const float4*)(sE + 128 + (warp << 5));

    for (int t = 0; t < NT; t++) {
        const float2 lg = g_lut2[sY[t] * 128 + tid];   // L2 load; consumed in phase 4

        // ---- phase 1: fp16 scores (2 rows) + exp + warp sum + gates_h (both cols) ----
        const float4* hv4 = (const float4*)(sXc + 64);
        float a0 = 0.f, a1 = 0.f, a2 = 0.f, a3 = 0.f;
        float b0 = 0.f, b1 = 0.f, b2 = 0.f, b3 = 0.f;
        float g00 = 0.f, g01 = 0.f, g10 = 0.f, g11 = 0.f;
#pragma unroll
        for (int i = 0; i < 8; i++) {
            const uint4 u0 = er0[i];
            const uint4 u1 = er1[i];
            const float4 ha = hv4[2 * i], hb = hv4[2 * i + 1];
            // row 0 dot
            float2 e;
            e = __half22float2(*(const __half2*)&u0.x); a0 = fmaf(e.x, ha.x, a0); a1 = fmaf(e.y, ha.y, a1);
            e = __half22float2(*(const __half2*)&u0.y); a2 = fmaf(e.x, ha.z, a2); a3 = fmaf(e.y, ha.w, a3);
            e = __half22float2(*(const __half2*)&u0.z); a0 = fmaf(e.x, hb.x, a0); a1 = fmaf(e.y, hb.y, a1);
            e = __half22float2(*(const __half2*)&u0.w); a2 = fmaf(e.x, hb.z, a2); a3 = fmaf(e.y, hb.w, a3);
            // row 1 dot
            e = __half22float2(*(const __half2*)&u1.x); b0 = fmaf(e.x, ha.x, b0); b1 = fmaf(e.y, ha.y, b1);
            e = __half22float2(*(const __half2*)&u1.y); b2 = fmaf(e.x, ha.z, b2); b3 = fmaf(e.y, ha.w, b3);
            e = __half22float2(*(const __half2*)&u1.z); b0 = fmaf(e.x, hb.x, b0); b1 = fmaf(e.y, hb.y, b1);
            e = __half22float2(*(const __half2*)&u1.w); b2 = fmaf(e.x, hb.z, b2); b3 = fmaf(e.y, hb.w, b3);
            // gates_h: k = 64+8i .. 71+8i, both columns (reuses ha/hb)
            float2 wv;
            wv = __half22float2(w2[64 + 8 * i + 0]); g00 = fmaf(ha.x, wv.x, g00); g10 = fmaf(ha.x, wv.y, g10);
            wv = __half22float2(w2[64 + 8 * i + 1]); g01 = fmaf(ha.y, wv.x, g01); g11 = fmaf(ha.y, wv.y, g11);
            wv = __half22float2(w2[64 + 8 * i + 2]); g00 = fmaf(ha.z, wv.x, g00); g10 = fmaf(ha.z, wv.y, g10);
            wv = __half22float2(w2[64 + 8 * i + 3]); g01 = fmaf(ha.w, wv.x, g01); g11 = fmaf(ha.w, wv.y, g11);
            wv = __half22float2(w2[64 + 8 * i + 4]); g00 = fmaf(hb.x, wv.x, g00); g10 = fmaf(hb.x, wv.y, g10);
            wv = __half22float2(w2[64 + 8 * i + 5]); g01 = fmaf(hb.y, wv.x, g01); g11 = fmaf(hb.y, wv.y, g11);
            wv = __half22float2(w2[64 + 8 * i + 6]); g00 = fmaf(hb.z, wv.x, g00); g10 = fmaf(hb.z, wv.y, g10);
            wv = __half22float2(w2[64 + 8 * i + 7]); g01 = fmaf(hb.w, wv.x, g01); g11 = fmaf(hb.w, wv.y, g11);
        }
        const float ghSum0 = g00 + g01;
        const float ghSum1 = g10 + g11;
        const float sc0 = fminf((a0 + a1) + (a2 + a3), 80.0f);  // |sc|<~45; NaN safety
        const float sc1 = fminf((b0 + b1) + (b2 + b3), 80.0f);
        const float ev0 = __expf(sc0);                          // shift-invariant softmax
        const float ev1 = __expf(sc1);
        sE[tid] = ev0;
        sE[128 + tid] = ev1;
        float ss = ev0 + ev1;
#pragma unroll
        for (int o = 16; o > 0; o >>= 1) ss += __shfl_xor_sync(0xffffffffu, ss, o);
        if (lane == 0) sWsum[warp] = ss;
        __syncwarp();      // phase 2 consumes only this warp's own sE slices

        // ---- phase 2: context partials over this warp's 64 s values ----
        float2 c0a = {0.f, 0.f}, c1a = {0.f, 0.f}, c2a = {0.f, 0.f}, c3a = {0.f, 0.f};
#pragma unroll
        for (int i4 = 0; i4 < 8; i4++) {
            const float4 e4 = ev4[i4];                      // broadcast
            const float2 p0 = __half22float2(e2p[(i4 * 4 + 0) * 36]);
            const float2 p1 = __half22float2(e2p[(i4 * 4 + 1) * 36]);
            const float2 p2 = __half22float2(e2p[(i4 * 4 + 2) * 36]);
            const float2 p3 = __half22float2(e2p[(i4 * 4 + 3) * 36]);
            c0a.x = fmaf(e4.x, p0.x, c0a.x); c0a.y = fmaf(e4.x, p0.y, c0a.y);
            c1a.x = fmaf(e4.y, p1.x, c1a.x); c1a.y = fmaf(e4.y, p1.y, c1a.y);
            c2a.x = fmaf(e4.z, p2.x, c2a.x); c2a.y = fmaf(e4.z, p2.y, c2a.y);
            c3a.x = fmaf(e4.w, p3.x, c3a.x); c3a.y = fmaf(e4.w, p3.y, c3a.y);
        }
#pragma unroll
        for (int i4 = 0; i4 < 8; i4++) {
            const float4 e4 = ev4B[i4];                     // broadcast (s block +128)
            const float2 p0 = __half22float2(e2pB[(i4 * 4 + 0) * 36]);
            const float2 p1 = __half22float2(e2pB[(i4 * 4 + 1) * 36]);
            const float2 p2 = __half22float2(e2pB[(i4 * 4 + 2) * 36]);
            const float2 p3 = __half22float2(e2pB[(i4 * 4 + 3) * 36]);
            c0a.x = fmaf(e4.x, p0.x, c0a.x); c0a.y = fmaf(e4.x, p0.y, c0a.y);
            c1a.x = fmaf(e4.y, p1.x, c1a.x); c1a.y = fmaf(e4.y, p1.y, c1a.y);
            c2a.x = fmaf(e4.z, p2.x, c2a.x); c2a.y = fmaf(e4.z, p2.y, c2a.y);
            c3a.x = fmaf(e4.w, p3.x, c3a.x); c3a.y = fmaf(e4.w, p3.y, c3a.y);
        }
        float2 cp;
        cp.x = (c0a.x + c1a.x) + (c2a.x + c3a.x);
        cp.y = (c0a.y + c1a.y) + (c2a.y + c3a.y);
        ((float2*)sCpart)[(warp << 5) + lane] = cp;
        __syncthreads();   // bar2

        // ---- phase 3: combine partials -> normalized context (tid<64) ----
        if (tid < 64) {
            const float cx = (sCpart[tid] + sCpart[64 + tid]) +
                             (sCpart[128 + tid] + sCpart[192 + tid]);
            const float sumE = (sWsum[0] + sWsum[1]) + (sWsum[2] + sWsum[3]);
            sXc[tid] = cx * __fdividef(1.0f, sumE);
        }
        __syncthreads();   // bar3

        // ---- phase 4: gates ctx-part, both columns (h-part precomputed) ----
        {
            float h00 = lg.x + ghSum0, h01 = 0.f;    // column j0
            float h10 = lg.y + ghSum1, h11 = 0.f;    // column j1
            const float4* xc4 = (const float4*)sXc;
#pragma unroll
            for (int i = 0; i < 16; i++) {
                const float4 x4 = xc4[i];
                float2 wv;
                wv = __half22float2(w2[4 * i + 0]); h00 = fmaf(x4.x, wv.x, h00); h10 = fmaf(x4.x, wv.y, h10);
                wv = __half22float2(w2[4 * i + 1]); h01 = fmaf(x4.y, wv.x, h01); h11 = fmaf(x4.y, wv.y, h11);
                wv = __half22float2(w2[4 * i + 2]); h00 = fmaf(x4.z, wv.x, h00); h10 = fmaf(x4.z, wv.y, h10);
                wv = __half22float2(w2[4 * i + 3]); h01 = fmaf(x4.w, wv.x, h01); h11 = fmaf(x4.w, wv.y, h11);
            }
            sE[tid] = h00 + h01;          // gates j0 in [0,128): i|f halves
            sE[128 + tid] = h10 + h11;    // gates j1 in [128,256): g|o halves
        }
        __syncthreads();   // bar4

        // ---- phase 5: LSTM cell update (tid<64), gate order i,f,g,o ----
        if (tid < 64) {
            const float gi = sE[tid],        gf = sE[64 + tid];
            const float gg = sE[128 + tid],  go = sE[192 + tid];
            const float cn = sigf(gf) * sCst[tid] + sigf(gi) * tanhfast(gg);
            const float hn = sigf(go) * tanhfast(cn);
            sCst[tid] = cn;
            sXc[64 + tid] = hn;
        }
        __syncthreads();   // bar5

        // ---- phase 6: logits partials, warp <-> 32-k chunk, lane <-> v ----
        {
            const int k0 = warp << 5;
            float lp0 = 0.f, lp1 = 0.f;
            const float4* x4p = (const float4*)(sXc + k0);
#pragma unroll
            for (int i = 0; i < 8; i++) {
                const float4 x4 = x4p[i];
                const float* fp = sFcP + (k0 + 4 * i) * 32 + lane;
                lp0 = fmaf(x4.x, fp[0],  lp0);
                lp1 = fmaf(x4.y, fp[32], lp1);
                lp0 = fmaf(x4.z, fp[64], lp0);
                lp1 = fmaf(x4.w, fp[96], lp1);
            }
            sLpart[(warp << 5) + lane] = lp0 + lp1;
        }
        __syncthreads();   // bar6

        // ---- phase 7: final reduce + store (warp 0) ----
        if (warp == 0 && lane < NV) {
            const float acc = sFcb[lane] +
                ((sLpart[lane] + sLpart[32 + lane]) + (sLpart[64 + lane] + sLpart[96 + lane]));
            out[((size_t)b * NT + t) * NV + lane] = acc;
        }
        // hazards: next ph1 writes sE after this loop's bar6 (ph5 reads were pre-bar5);
        // next ph6 writes sLpart with bar2..bar5 separating this ph7's reads
    }
}

extern "C" void kernel_launch(void* const* d_in, const int* in_sizes, int n_in,
                              void* d_out, int out_size) {
    const int*   y      = (const int*)d_in[0];
    const float* h0     = (const float*)d_in[1];
    const float* c0     = (const float*)d_in[2];
    const float* encout = (const float*)d_in[3];
    const float* emb    = (const float*)d_in[4];
    const float* W_ih   = (const float*)d_in[5];
    const float* W_hh   = (const float*)d_in[6];
    const float* b_ih   = (const float*)d_in[7];
    const float* b_hh   = (const float*)d_in[8];
    const float* fc_W   = (const float*)d_in[9];
    const float* fc_b   = (const float*)d_in[10];
    float* out = (float*)d_out;

    cudaFuncSetAttribute(decoder_kernel, cudaFuncAttributeMaxDynamicSharedMemorySize, SMEM_BYTES);

    setup_kernel<<<NV + 2, 128>>>(emb, W_ih, W_hh, b_ih, b_hh, fc_W, fc_b);
    decoder_kernel<<<NB, 128, SMEM_BYTES>>>(y, h0, c0, encout, out);
}

// round 14
// speedup vs baseline: 2.1594x; 1.0183x over previous
#include <cuda_runtime.h>
#include <cuda_fp16.h>

#define NB 2048
#define NT 128
#define NS 256
#define NH 64
#define NE 32
#define NV 29

// ---------------- precomputed constants (filled by setup_kernel) ----------------
// thread t (0..127): hh = t>>1, c = t&1; gate columns j0 = hh + 64c, j1 = 128 + hh + 64c.
// (even lane: i_hh and g_hh; odd lane: f_hh and o_hh)
__device__ __half2 g_wTh[128 * 128];  // [k][t] = half2(W[k][j0], W[k][j1]); k<64: W_ih ctx, k>=64: W_hh
__device__ float2  g_lut2[NV * 128];  // [v][t] = (lut[v][j0], lut[v][j1])
__device__ float   g_fcP[128 * 32];   // [k][v]: xc order [context(0..63), h_new(64..127)]; v>=29 -> 0
__device__ float   g_fcb[32];

__device__ __forceinline__ float sigf(float x) {
    return __fdividef(1.0f, 1.0f + __expf(-x));
}
__device__ __forceinline__ float tanhfast(float x) {
    return 1.0f - __fdividef(2.0f, __expf(2.0f * x) + 1.0f);
}

__global__ void setup_kernel(const float* __restrict__ emb, const float* __restrict__ W_ih,
                             const float* __restrict__ W_hh, const float* __restrict__ b_ih,
                             const float* __restrict__ b_hh, const float* __restrict__ fc_W,
                             const float* __restrict__ fc_b) {
    const int t = threadIdx.x;     // 0..127
    const int blk = blockIdx.x;
    const int hh = t >> 1, c = t & 1;
    const int j0 = hh + 64 * c;
    const int j1 = 128 + hh + 64 * c;
    if (blk < NV) {
        float s[2];
        const int js[2] = { j0, j1 };
#pragma unroll
        for (int q = 0; q < 2; q++) {
            const int j = js[q];
            float acc = b_ih[j] + b_hh[j];
#pragma unroll
            for (int e = 0; e < NE; e++) acc += emb[blk * NE + e] * W_ih[j * (NE + NH) + e];
            s[q] = acc;
        }
        g_lut2[blk * 128 + t] = make_float2(s[0], s[1]);
    } else if (blk == NV) {
        for (int k = 0; k < 128; k++) {
            float w0, w1;
            if (k < 64) {
                w0 = W_ih[j0 * (NE + NH) + NE + k];
                w1 = W_ih[j1 * (NE + NH) + NE + k];
            } else {
                w0 = W_hh[j0 * NH + (k - 64)];
                w1 = W_hh[j1 * NH + (k - 64)];
            }
            g_wTh[k * 128 + t] = __floats2half2_rn(w0, w1);
        }
    } else {
        for (int idx = t; idx < 4096; idx += 128) {
            const int k = idx >> 5, v = idx & 31;
            float val = 0.0f;
            if (v < NV) val = (k < 64) ? fc_W[v * 128 + 64 + k] : fc_W[v * 128 + (k - 64)];
            g_fcP[idx] = val;
        }
        if (t < 32) g_fcb[t] = (t < NV) ? fc_b[t] : 0.0f;
    }
}

// ---------------- smem layout (offsets in floats), 1 row per CTA, 128 threads ----------------
#define OFF_ENC16  0        // 256*72 halves = 9216 floats
#define OFF_FCP    9216     // 4096
#define OFF_CTX    13312    // 64
#define OFF_HBUF   13376    // 2 * 64 (h ping-pong)
#define OFF_CST    13504    // 64
#define OFF_E      13568    // 256  softmax weights (warp-private)
#define OFF_CPART  13824    // 256
#define OFF_LPART  14080    // 128
#define OFF_WSUM   14208    // 8 (4 used)
#define OFF_FCB    14216    // 32
#define OFF_Y      14248    // 128 ints
#define SMEM_FLOATS 14376
#define SMEM_BYTES (SMEM_FLOATS * 4)   // 57504 -> 2 CTAs/SM = 115 KB

__global__ void __launch_bounds__(128, 2)
decoder_kernel(const int* __restrict__ y, const float* __restrict__ h0,
               const float* __restrict__ c0, const float* __restrict__ enc,
               float* __restrict__ out) {
    extern __shared__ float sm[];
    __half*  sEnc16 = (__half*)(sm + OFF_ENC16);
    float*   sFcP   = sm + OFF_FCP;
    float*   sCtx   = sm + OFF_CTX;
    float*   sHbuf  = sm + OFF_HBUF;
    float*   sCst   = sm + OFF_CST;
    float*   sE     = sm + OFF_E;
    float*   sCpart = sm + OFF_CPART;
    float*   sLpart = sm + OFF_LPART;
    float*   sWsum  = sm + OFF_WSUM;
    float*   sFcb   = sm + OFF_FCB;
    int*     sY     = (int*)(sm + OFF_Y);

    const int b = blockIdx.x, tid = threadIdx.x;   // 128 threads
    const int lane = tid & 31, warp = tid >> 5;    // 4 warps

    // one-time loads
    const float* encb = enc + (size_t)b * (NS * NH);
    for (int idx = tid; idx < NS * NH; idx += 128) {
        const int s = idx >> 6, h = idx & 63;
        sEnc16[s * 72 + h] = __float2half(encb[idx]);
    }
    for (int idx = tid; idx < 4096; idx += 128) sFcP[idx] = g_fcP[idx];
    if (tid < 64) { sHbuf[tid] = h0[b * 64 + tid]; sCst[tid] = c0[b * 64 + tid]; }
    sY[tid] = y[b * 128 + tid];
    if (tid < 32) sFcb[tid] = g_fcb[tid];

    // per-thread packed gate weights for columns (j0, j1)
    __half2 w2[128];
#pragma unroll
    for (int k = 0; k < 128; k++) w2[k] = g_wTh[k * 128 + tid];
    __syncthreads();

    // scores: thread owns encoder rows s = tid and s = tid+128
    const uint4* er0 = (const uint4*)(sEnc16 + tid * 72);
    const uint4* er1 = er0 + 1152;                 // +128 rows * 72 halves
    // context: warp w <-> s blocks [32w,32w+32) and [128+32w,...), lane <-> h-pair
    const __half2* e2p  = (const __half2*)sEnc16 + warp * (32 * 36) + lane;
    const __half2* e2pB = e2p + 128 * 36;
    const float4*  ev4  = (const float4*)(sE + (warp << 5));
    const float4*  ev4B = (const float4*)(sE + 128 + (warp << 5));
    const int hh = tid >> 1;

    for (int t = 0; t < NT; t++) {
        const float* hP = sHbuf + (t & 1) * 64;        // h for this step
        float*       hN = sHbuf + ((t + 1) & 1) * 64;  // h_new written here
        const float2 lg = g_lut2[sY[t] * 128 + tid];   // L2 load; consumed in phase 4

        // ---- phase 1: fp16 scores (2 rows) + exp + gates_h (both cols) ----
        const float4* hv4 = (const float4*)hP;
        float a0 = 0.f, a1 = 0.f, a2 = 0.f, a3 = 0.f;
        float b0 = 0.f, b1 = 0.f, b2 = 0.f, b3 = 0.f;
        float g00 = 0.f, g01 = 0.f, g10 = 0.f, g11 = 0.f;
#pragma unroll
        for (int i = 0; i < 8; i++) {
            const uint4 u0 = er0[i];
            const uint4 u1 = er1[i];
            const float4 ha = hv4[2 * i], hb = hv4[2 * i + 1];
            float2 e;
            e = __half22float2(*(const __half2*)&u0.x); a0 = fmaf(e.x, ha.x, a0); a1 = fmaf(e.y, ha.y, a1);
            e = __half22float2(*(const __half2*)&u0.y); a2 = fmaf(e.x, ha.z, a2); a3 = fmaf(e.y, ha.w, a3);
            e = __half22float2(*(const __half2*)&u0.z); a0 = fmaf(e.x, hb.x, a0); a1 = fmaf(e.y, hb.y, a1);
            e = __half22float2(*(const __half2*)&u0.w); a2 = fmaf(e.x, hb.z, a2); a3 = fmaf(e.y, hb.w, a3);
            e = __half22float2(*(const __half2*)&u1.x); b0 = fmaf(e.x, ha.x, b0); b1 = fmaf(e.y, ha.y, b1);
            e = __half22float2(*(const __half2*)&u1.y); b2 = fmaf(e.x, ha.z, b2); b3 = fmaf(e.y, ha.w, b3);
            e = __half22float2(*(const __half2*)&u1.z); b0 = fmaf(e.x, hb.x, b0); b1 = fmaf(e.y, hb.y, b1);
            e = __half22float2(*(const __half2*)&u1.w); b2 = fmaf(e.x, hb.z, b2); b3 = fmaf(e.y, hb.w, b3);
            float2 wv;
            wv = __half22float2(w2[64 + 8 * i + 0]); g00 = fmaf(ha.x, wv.x, g00); g10 = fmaf(ha.x, wv.y, g10);
            wv = __half22float2(w2[64 + 8 * i + 1]); g01 = fmaf(ha.y, wv.x, g01); g11 = fmaf(ha.y, wv.y, g11);
            wv = __half22float2(w2[64 + 8 * i + 2]); g00 = fmaf(ha.z, wv.x, g00); g10 = fmaf(ha.z, wv.y, g10);
            wv = __half22float2(w2[64 + 8 * i + 3]); g01 = fmaf(ha.w, wv.x, g01); g11 = fmaf(ha.w, wv.y, g11);
            wv = __half22float2(w2[64 + 8 * i + 4]); g00 = fmaf(hb.x, wv.x, g00); g10 = fmaf(hb.x, wv.y, g10);
            wv = __half22float2(w2[64 + 8 * i + 5]); g01 = fmaf(hb.y, wv.x, g01); g11 = fmaf(hb.y, wv.y, g11);
            wv = __half22float2(w2[64 + 8 * i + 6]); g00 = fmaf(hb.z, wv.x, g00); g10 = fmaf(hb.z, wv.y, g10);
            wv = __half22float2(w2[64 + 8 * i + 7]); g01 = fmaf(hb.w, wv.x, g01); g11 = fmaf(hb.w, wv.y, g11);
        }
        const float ghSum0 = g00 + g01;
        const float ghSum1 = g10 + g11;
        const float sc0 = fminf((a0 + a1) + (a2 + a3), 80.0f);  // |sc|<~45; NaN safety
        const float sc1 = fminf((b0 + b1) + (b2 + b3), 80.0f);
        const float ev0 = __expf(sc0);                          // shift-invariant softmax
        const float ev1 = __expf(sc1);
        sE[tid] = ev0;
        sE[128 + tid] = ev1;
        __syncwarp();      // phase 2 consumes only this warp's own sE slices

        // ---- phase 2: context partials over this warp's 64 s values ----
        float2 c0a = {0.f, 0.f}, c1a = {0.f, 0.f}, c2a = {0.f, 0.f}, c3a = {0.f, 0.f};
#pragma unroll
        for (int i4 = 0; i4 < 8; i4++) {
            const float4 e4 = ev4[i4];                      // broadcast
            const float2 p0 = __half22float2(e2p[(i4 * 4 + 0) * 36]);
            const float2 p1 = __half22float2(e2p[(i4 * 4 + 1) * 36]);
            const float2 p2 = __half22float2(e2p[(i4 * 4 + 2) * 36]);
            const float2 p3 = __half22float2(e2p[(i4 * 4 + 3) * 36]);
            c0a.x = fmaf(e4.x, p0.x, c0a.x); c0a.y = fmaf(e4.x, p0.y, c0a.y);
            c1a.x = fmaf(e4.y, p1.x, c1a.x); c1a.y = fmaf(e4.y, p1.y, c1a.y);
            c2a.x = fmaf(e4.z, p2.x, c2a.x); c2a.y = fmaf(e4.z, p2.y, c2a.y);
            c3a.x = fmaf(e4.w, p3.x, c3a.x); c3a.y = fmaf(e4.w, p3.y, c3a.y);
        }
#pragma unroll
        for (int i4 = 0; i4 < 8; i4++) {
            const float4 e4 = ev4B[i4];                     // broadcast (s block +128)
            const float2 p0 = __half22float2(e2pB[(i4 * 4 + 0) * 36]);
            const float2 p1 = __half22float2(e2pB[(i4 * 4 + 1) * 36]);
            const float2 p2 = __half22float2(e2pB[(i4 * 4 + 2) * 36]);
            const float2 p3 = __half22float2(e2pB[(i4 * 4 + 3) * 36]);
            c0a.x = fmaf(e4.x, p0.x, c0a.x); c0a.y = fmaf(e4.x, p0.y, c0a.y);
            c1a.x = fmaf(e4.y, p1.x, c1a.x); c1a.y = fmaf(e4.y, p1.y, c1a.y);
            c2a.x = fmaf(e4.z, p2.x, c2a.x); c2a.y = fmaf(e4.z, p2.y, c2a.y);
            c3a.x = fmaf(e4.w, p3.x, c3a.x); c3a.y = fmaf(e4.w, p3.y, c3a.y);
        }
        float2 cp;
        cp.x = (c0a.x + c1a.x) + (c2a.x + c3a.x);
        cp.y = (c0a.y + c1a.y) + (c2a.y + c3a.y);
        ((float2*)sCpart)[(warp << 5) + lane] = cp;
        // softmax sum tree AFTER ph2 (overlaps ph2 LDS/FMA latency); result needed post-bar2
        float ss = ev0 + ev1;
#pragma unroll
        for (int o = 16; o > 0; o >>= 1) ss += __shfl_xor_sync(0xffffffffu, ss, o);
        if (lane == 0) sWsum[warp] = ss;
        __syncthreads();   // bar2

        // ---- phase 3: combine partials -> normalized context (tid<64) ----
        if (tid < 64) {
            const float cx = (sCpart[tid] + sCpart[64 + tid]) +
                             (sCpart[128 + tid] + sCpart[192 + tid]);
            const float sumE = (sWsum[0] + sWsum[1]) + (sWsum[2] + sWsum[3]);
            sCtx[tid] = cx * __fdividef(1.0f, sumE);
        }
        __syncthreads();   // bar3

        // ---- phase 4: gates ctx-part + inline cell via lane-pair shfl ----
        {
            float h00 = lg.x + ghSum0, h01 = 0.f;    // column j0
            float h10 = lg.y + ghSum1, h11 = 0.f;    // column j1
            const float4* xc4 = (const float4*)sCtx;
#pragma unroll
            for (int i = 0; i < 16; i++) {
                const float4 x4 = xc4[i];
                float2 wv;
                wv = __half22float2(w2[4 * i + 0]); h00 = fmaf(x4.x, wv.x, h00); h10 = fmaf(x4.x, wv.y, h10);
                wv = __half22float2(w2[4 * i + 1]); h01 = fmaf(x4.y, wv.x, h01); h11 = fmaf(x4.y, wv.y, h11);
                wv = __half22float2(w2[4 * i + 2]); h00 = fmaf(x4.z, wv.x, h00); h10 = fmaf(x4.z, wv.y, h10);
                wv = __half22float2(w2[4 * i + 3]); h01 = fmaf(x4.w, wv.x, h01); h11 = fmaf(x4.w, wv.y, h11);
            }
            const float gate0 = h00 + h01;   // even: i_hh, odd: f_hh
            const float gate1 = h10 + h11;   // even: g_hh, odd: o_hh
            const float oth0 = __shfl_xor_sync(0xffffffffu, gate0, 1);
            const float oth1 = __shfl_xor_sync(0xffffffffu, gate1, 1);
            if ((tid & 1) == 0) {
                const float gi = gate0, gf = oth0, gg = gate1, go = oth1;
                const float cn = sigf(gf) * sCst[hh] + sigf(gi) * tanhfast(gg);
                const float hn = sigf(go) * tanhfast(cn);
                sCst[hh] = cn;
                hN[hh] = hn;      // ping-pong: no race with hP readers
            }
        }
        __syncthreads();   // bar4 (cell results visible)

        // ---- phase 5: logits partials, warp <-> 32-k chunk, lane <-> v ----
        {
            const int k0 = warp << 5;
            const float4* x4p = (warp < 2) ? (const float4*)(sCtx + k0)
                                           : (const float4*)(hN + (k0 - 64));
            float lp0 = 0.f, lp1 = 0.f;
#pragma unroll
            for (int i = 0; i < 8; i++) {
                const float4 x4 = x4p[i];
                const float* fp = sFcP + (k0 + 4 * i) * 32 + lane;
                lp0 = fmaf(x4.x, fp[0],  lp0);
                lp1 = fmaf(x4.y, fp[32], lp1);
                lp0 = fmaf(x4.z, fp[64], lp0);
                lp1 = fmaf(x4.w, fp[96], lp1);
            }
            sLpart[(warp << 5) + lane] = lp0 + lp1;
        }
        __syncthreads();   // bar5

        // ---- phase 6: final reduce + store (warp 0) ----
        if (warp == 0 && lane < NV) {
            const float acc = sFcb[lane] +
                ((sLpart[lane] + sLpart[32 + lane]) + (sLpart[64 + lane] + sLpart[96 + lane]));
            out[((size_t)b * NT + t) * NV + lane] = acc;
        }
        // hazards: sE is warp-private (ph1 writes, ph2 same-warp reads) -> no cross-step bar;
        // next ph2 writes sCpart after this ph3 reads (bar3, bar4, bar5 between);
        // next ph5 writes sLpart after this ph6 reads (bar2..bar4 between);
        // next ph3 writes sCtx after this ph5 reads (bar5 + next bar2 between);
        // cell writes hN, readers of hP unaffected (ping-pong)
    }
}

extern "C" void kernel_launch(void* const* d_in, const int* in_sizes, int n_in,
                              void* d_out, int out_size) {
    const int*   y      = (const int*)d_in[0];
    const float* h0     = (const float*)d_in[1];
    const float* c0     = (const float*)d_in[2];
    const float* encout = (const float*)d_in[3];
    const float* emb    = (const float*)d_in[4];
    const float* W_ih   = (const float*)d_in[5];
    const float* W_hh   = (const float*)d_in[6];
    const float* b_ih   = (const float*)d_in[7];
    const float* b_hh   = (const float*)d_in[8];
    const float* fc_W   = (const float*)d_in[9];
    const float* fc_b   = (const float*)d_in[10];
    float* out = (float*)d_out;

    cudaFuncSetAttribute(decoder_kernel, cudaFuncAttributeMaxDynamicSharedMemorySize, SMEM_BYTES);

    setup_kernel<<<NV + 2, 128>>>(emb, W_ih, W_hh, b_ih, b_hh, fc_W, fc_b);
    decoder_kernel<<<NB, 128, SMEM_BYTES>>>(y, h0, c0, encout, out);
}